// round 9
// baseline (speedup 1.0000x reference)
#include <cuda_runtime.h>

#define IMG_H 2048
#define IMG_W 2048
#define HW (IMG_H * IMG_W)
#define NCH 3
#define ITER 8

// Ping-pong scratch planes (CHW, planar). Device globals: allowed scratch.
__device__ float g_bufA[NCH * HW];
__device__ float g_bufB[NCH * HW];

typedef unsigned long long ull;

// ---------------- packed f32x2 helpers (Blackwell dual-FP32) ----------------
__device__ __forceinline__ ull pk(float lo, float hi) {
    ull r; asm("mov.b64 %0, {%1, %2};" : "=l"(r) : "f"(lo), "f"(hi)); return r;
}
__device__ __forceinline__ void upk(ull v, float& lo, float& hi) {
    asm("mov.b64 {%0, %1}, %2;" : "=f"(lo), "=f"(hi) : "l"(v));
}
__device__ __forceinline__ ull add2(ull a, ull b) {
    ull r; asm("add.rn.f32x2 %0, %1, %2;" : "=l"(r) : "l"(a), "l"(b)); return r;
}
__device__ __forceinline__ ull mul2(ull a, ull b) {
    ull r; asm("mul.rn.f32x2 %0, %1, %2;" : "=l"(r) : "l"(a), "l"(b)); return r;
}
__device__ __forceinline__ ull fma2(ull a, ull b, ull c) {
    ull r; asm("fma.rn.f32x2 %0, %1, %2, %3;" : "=l"(r) : "l"(a), "l"(b), "l"(c)); return r;
}
// keep `a` on tie (earlier kernel has priority) -> FSETP(|.|)+FSEL, 2 ops
__device__ __forceinline__ float selmin(float a, float b) {
    return (fabsf(b) < fabsf(a)) ? b : a;
}

// ---------------------------------------------------------------------------
// HWC -> CHW planar (float4-vectorized, 4 pixels/thread)
// ---------------------------------------------------------------------------
__global__ void hwc2chw_kernel(const float* __restrict__ img) {
    int p = blockIdx.x * blockDim.x + threadIdx.x;
    if (p >= HW / 4) return;
    const float4* in = (const float4*)img + 3 * p;
    float4 a = in[0], b = in[1], c = in[2];
    ((float4*)(g_bufA + 0 * HW))[p] = make_float4(a.x, a.w, b.z, c.y);
    ((float4*)(g_bufA + 1 * HW))[p] = make_float4(a.y, b.x, b.w, c.z);
    ((float4*)(g_bufA + 2 * HW))[p] = make_float4(a.z, b.y, c.x, c.w);
}

// ---------------------------------------------------------------------------
// One SWF iteration. Tile: 128 wide x 32 high per block (32,4)=128 threads.
// Each thread: 4 adjacent columns (two packed f32x2 streams) x 8 rows.
// Channels per row: H0=(h0,h1) H1=(h2,h3) H2=(h4,h5) (h_i = v_i+v_{i+1}+v_{i+2})
//                   C0=(v2,v3) C1=(v4,v5)
// Vertical: B(p)=H(p+2)+H(p+3)+H(p+4) fresh, A(p)=B(p-2) from a 2-slot pipe.
// ---------------------------------------------------------------------------
#define TX 128
#define TY 32
#define PY 8
#define TROWS 36
#define STRIDE 136

__global__ __launch_bounds__(128, 8) void swf_step_kernel(int srcIsA) {
    const float* __restrict__ src = (srcIsA ? g_bufA : g_bufB) + blockIdx.z * HW;
    float* __restrict__ dst       = (srcIsA ? g_bufB : g_bufA) + blockIdx.z * HW;

    __shared__ float tile[TROWS * STRIDE];

    const int tx = threadIdx.x, ty = threadIdx.y;
    const int bx = blockIdx.x * TX, by = blockIdx.y * TY;

    const bool interior = (blockIdx.x > 0) && (blockIdx.x < gridDim.x - 1) &&
                          (blockIdx.y > 0) && (blockIdx.y < gridDim.y - 1);

    if (interior) {
        const float* g = src + (by - 2) * IMG_W + (bx - 2);
        #pragma unroll
        for (int r = ty; r < TROWS; r += 4) {
            *(float2*)&tile[r * STRIDE + 4 + 2 * tx]   = *(const float2*)(g + r * IMG_W + 2 * tx);
            *(float2*)&tile[r * STRIDE + 68 + 2 * tx]  = *(const float2*)(g + r * IMG_W + 64 + 2 * tx);
            if (tx < 2)
                *(float2*)&tile[r * STRIDE + 132 + 2 * tx] = *(const float2*)(g + r * IMG_W + 128 + 2 * tx);
        }
    } else {
        #pragma unroll
        for (int r = ty; r < TROWS; r += 4) {
            int gy = min(max(by + r - 2, 0), IMG_H - 1);
            const float* grow = src + gy * IMG_W;
            #pragma unroll
            for (int k = 0; k < 2; k++) {
                int idx = tx + 32 * k;
                int c0 = min(max(bx - 2 + 2 * idx, 0), IMG_W - 1);
                int c1 = min(max(bx - 1 + 2 * idx, 0), IMG_W - 1);
                *(float2*)&tile[r * STRIDE + 4 + 2 * idx] = make_float2(grow[c0], grow[c1]);
            }
            if (tx < 2) {
                int idx = tx + 64;
                int c0 = min(max(bx - 2 + 2 * idx, 0), IMG_W - 1);
                int c1 = min(max(bx - 1 + 2 * idx, 0), IMG_W - 1);
                *(float2*)&tile[r * STRIDE + 4 + 2 * idx] = make_float2(grow[c0], grow[c1]);
            }
        }
    }
    __syncthreads();

    const int row0 = ty * PY;

    auto loadrow = [&](int r, ull* o) {
        const float* base = &tile[r * STRIDE + 4 * tx + 4];
        float4 q0 = *(const float4*)(base);      // v0 v1 v2 v3
        float4 q1 = *(const float4*)(base + 4);  // v4 v5 v6 v7
        float s0 = q0.x + q0.y, s1 = q0.y + q0.z, s2 = q0.z + q0.w;
        float s3 = q0.w + q1.x, s4 = q1.x + q1.y, s5 = q1.y + q1.z;
        o[0] = pk(s0 + q0.z, s1 + q0.w);   // H0
        o[1] = pk(s2 + q1.x, s3 + q1.y);   // H1
        o[2] = pk(s4 + q1.z, s5 + q1.w);   // H2
        o[3] = pk(q0.z, q0.w);             // C0
        o[4] = pk(q1.x, q1.y);             // C1
    };

    const ull K9    = 0x4110000041100000ULL;  // ( 9, 9)
    const ull Km9   = 0xC1100000C1100000ULL;  // (-9,-9)
    const ull K15   = 0x4170000041700000ULL;  // (15,15)
    const ull Km135 = 0xC3070000C3070000ULL;  // (-135,-135)
    const float INV135 = 1.0f / 135.0f;

    // ---- prologue: rows 0..3 (tile-local). Ring slot = row_index % 3. ----
    ull R[3][5], Ap[2][5];
    {
        ull t0[5], t1[5];
        loadrow(row0 + 0, t0);
        loadrow(row0 + 1, t1);
        loadrow(row0 + 2, R[2]);   // row 2 -> slot 2
        loadrow(row0 + 3, R[0]);   // row 3 -> slot 0
        #pragma unroll
        for (int ch = 0; ch < 5; ch++) {
            ull s = add2(t1[ch], R[2][ch]);
            Ap[0][ch] = add2(t0[ch], s);        // V(0..2) = A(0)
            Ap[1][ch] = add2(s, R[0][ch]);      // V(1..3) = A(1)
        }
    }

    float* drow = dst + (by + row0) * IMG_W + bx + 4 * tx;

    #pragma unroll
    for (int p = 0; p < PY; p++) {
        const int snew = (p + 4) % 3;   // incoming row p+4
        const int smid = (p + 2) % 3;   // middle row p+2
        const int s3   = (p + 3) % 3;   // row p+3

        loadrow(row0 + p + 4, R[snew]);

        ull B[5];
        #pragma unroll
        for (int ch = 0; ch < 5; ch++)
            B[ch] = add2(add2(R[smid][ch], R[s3][ch]), R[snew][ch]);  // V(p+2..p+4)

        const ull* A = Ap[p & 1];
        const ull* M = R[smid];

        // shared window sums across both streams
        ull AB0 = add2(A[0], B[0]);
        ull AB1 = add2(A[1], B[1]);
        ull AB2 = add2(A[2], B[2]);
        ull A01 = add2(A[0], A[1]);
        ull A12 = add2(A[1], A[2]);
        ull B01 = add2(B[0], B[1]);
        ull B12 = add2(B[1], B[2]);

        float4 outv;

        {   // stream 0: cols c0,c1  (Hl=H0, Hr=H1, cc=C0)
            ull negC = mul2(M[3], Km135);
            ull eL  = fma2(M[0], Km9, fma2(AB0, K9, negC));
            ull eR  = fma2(M[1], Km9, fma2(AB1, K9, negC));
            ull eU  = fma2(A[3], Km9, fma2(A01, K9, negC));
            ull eD  = fma2(B[3], Km9, fma2(B01, K9, negC));
            ull eNW = fma2(A[0], K15, negC);
            ull eNE = fma2(A[1], K15, negC);
            ull eSW = fma2(B[0], K15, negC);
            ull eSE = fma2(B[1], K15, negC);

            float c0, c1;   upk(M[3], c0, c1);
            float l0, l1;   upk(eL,  l0, l1);
            float r0, r1;   upk(eR,  r0, r1);
            float u0, u1;   upk(eU,  u0, u1);
            float d0, d1;   upk(eD,  d0, d1);
            float nw0, nw1; upk(eNW, nw0, nw1);
            float ne0, ne1; upk(eNE, ne0, ne1);
            float sw0, sw1; upk(eSW, sw0, sw1);
            float se0, se1; upk(eSE, se0, se1);

            float m0 = selmin(selmin(selmin(l0, r0), selmin(u0, d0)),
                              selmin(selmin(nw0, ne0), selmin(sw0, se0)));
            float m1 = selmin(selmin(selmin(l1, r1), selmin(u1, d1)),
                              selmin(selmin(nw1, ne1), selmin(sw1, se1)));
            outv.x = fmaf(m0, INV135, c0);
            outv.y = fmaf(m1, INV135, c1);
        }
        {   // stream 1: cols c2,c3  (Hl=H1, Hr=H2, cc=C1)
            ull negC = mul2(M[4], Km135);
            ull eL  = fma2(M[1], Km9, fma2(AB1, K9, negC));
            ull eR  = fma2(M[2], Km9, fma2(AB2, K9, negC));
            ull eU  = fma2(A[4], Km9, fma2(A12, K9, negC));
            ull eD  = fma2(B[4], Km9, fma2(B12, K9, negC));
            ull eNW = fma2(A[1], K15, negC);
            ull eNE = fma2(A[2], K15, negC);
            ull eSW = fma2(B[1], K15, negC);
            ull eSE = fma2(B[2], K15, negC);

            float c0, c1;   upk(M[4], c0, c1);
            float l0, l1;   upk(eL,  l0, l1);
            float r0, r1;   upk(eR,  r0, r1);
            float u0, u1;   upk(eU,  u0, u1);
            float d0, d1;   upk(eD,  d0, d1);
            float nw0, nw1; upk(eNW, nw0, nw1);
            float ne0, ne1; upk(eNE, ne0, ne1);
            float sw0, sw1; upk(eSW, sw0, sw1);
            float se0, se1; upk(eSE, se0, se1);

            float m0 = selmin(selmin(selmin(l0, r0), selmin(u0, d0)),
                              selmin(selmin(nw0, ne0), selmin(sw0, se0)));
            float m1 = selmin(selmin(selmin(l1, r1), selmin(u1, d1)),
                              selmin(selmin(nw1, ne1), selmin(sw1, se1)));
            outv.z = fmaf(m0, INV135, c0);
            outv.w = fmaf(m1, INV135, c1);
        }

        *(float4*)drow = outv;
        drow += IMG_W;

        #pragma unroll
        for (int ch = 0; ch < 5; ch++) Ap[p & 1][ch] = B[ch];  // A(p+2) = B(p)
    }
}

// ---------------------------------------------------------------------------
// |x0 - res| clipped, CHW -> HWC (float4-vectorized, 4 pixels/thread)
// ---------------------------------------------------------------------------
__global__ void finalize_kernel(const float* __restrict__ img, float* __restrict__ out) {
    int p = blockIdx.x * blockDim.x + threadIdx.x;
    if (p >= HW / 4) return;
    const float4* in = (const float4*)img + 3 * p;
    float4 a = in[0], b = in[1], c = in[2];
    float4 r0 = ((const float4*)(g_bufA + 0 * HW))[p];
    float4 r1 = ((const float4*)(g_bufA + 1 * HW))[p];
    float4 r2 = ((const float4*)(g_bufA + 2 * HW))[p];
    float4 o0 = make_float4(fminf(fabsf(a.x - r0.x), 255.f), fminf(fabsf(a.y - r1.x), 255.f),
                            fminf(fabsf(a.z - r2.x), 255.f), fminf(fabsf(a.w - r0.y), 255.f));
    float4 o1 = make_float4(fminf(fabsf(b.x - r1.y), 255.f), fminf(fabsf(b.y - r2.y), 255.f),
                            fminf(fabsf(b.z - r0.z), 255.f), fminf(fabsf(b.w - r1.z), 255.f));
    float4 o2 = make_float4(fminf(fabsf(c.x - r2.z), 255.f), fminf(fabsf(c.y - r0.w), 255.f),
                            fminf(fabsf(c.z - r1.w), 255.f), fminf(fabsf(c.w - r2.w), 255.f));
    float4* op = (float4*)out + 3 * p;
    op[0] = o0; op[1] = o1; op[2] = o2;
}

// ---------------------------------------------------------------------------
extern "C" void kernel_launch(void* const* d_in, const int* in_sizes, int n_in,
                              void* d_out, int out_size) {
    const float* img = (const float*)d_in[0];
    float* out = (float*)d_out;

    hwc2chw_kernel<<<HW / 4 / 256, 256>>>(img);

    dim3 grid(IMG_W / TX, IMG_H / TY, NCH);
    dim3 block(32, 4);
    for (int it = 0; it < ITER; it++) {
        swf_step_kernel<<<grid, block>>>((it & 1) == 0 ? 1 : 0);
    }
    // After 8 iterations (even), result is back in g_bufA.
    finalize_kernel<<<HW / 4 / 256, 256>>>(img, out);
}

// round 10
// speedup vs baseline: 1.3604x; 1.3604x over previous
#include <cuda_runtime.h>

#define IMG_H 2048
#define IMG_W 2048
#define HW (IMG_H * IMG_W)
#define NCH 3
#define ITER 8

// Ping-pong scratch planes (CHW, planar). Device globals: allowed scratch.
__device__ float g_bufA[NCH * HW];
__device__ float g_bufB[NCH * HW];

typedef unsigned long long ull;

// ---------------- packed f32x2 helpers (Blackwell dual-FP32) ----------------
__device__ __forceinline__ ull pk(float lo, float hi) {
    ull r; asm("mov.b64 %0, {%1, %2};" : "=l"(r) : "f"(lo), "f"(hi)); return r;
}
__device__ __forceinline__ void upk(ull v, float& lo, float& hi) {
    asm("mov.b64 {%0, %1}, %2;" : "=f"(lo), "=f"(hi) : "l"(v));
}
__device__ __forceinline__ ull add2(ull a, ull b) {
    ull r; asm("add.rn.f32x2 %0, %1, %2;" : "=l"(r) : "l"(a), "l"(b)); return r;
}
__device__ __forceinline__ ull mul2(ull a, ull b) {
    ull r; asm("mul.rn.f32x2 %0, %1, %2;" : "=l"(r) : "l"(a), "l"(b)); return r;
}
__device__ __forceinline__ ull fma2(ull a, ull b, ull c) {
    ull r; asm("fma.rn.f32x2 %0, %1, %2, %3;" : "=l"(r) : "l"(a), "l"(b), "l"(c)); return r;
}
// keep `a` on tie (earlier kernel has priority) -> FSETP(|.|)+FSEL, 2 ops
__device__ __forceinline__ float selmin(float a, float b) {
    return (fabsf(b) < fabsf(a)) ? b : a;
}

// ---------------------------------------------------------------------------
// HWC -> CHW planar (float4-vectorized, 4 pixels/thread)
// ---------------------------------------------------------------------------
__global__ void hwc2chw_kernel(const float* __restrict__ img) {
    int p = blockIdx.x * blockDim.x + threadIdx.x;
    if (p >= HW / 4) return;
    const float4* in = (const float4*)img + 3 * p;
    float4 a = in[0], b = in[1], c = in[2];
    ((float4*)(g_bufA + 0 * HW))[p] = make_float4(a.x, a.w, b.z, c.y);
    ((float4*)(g_bufA + 1 * HW))[p] = make_float4(a.y, b.x, b.w, c.z);
    ((float4*)(g_bufA + 2 * HW))[p] = make_float4(a.z, b.y, c.x, c.w);
}

// ---------------------------------------------------------------------------
// One SWF iteration. Tile: 128 wide x 32 high per block (32,4)=128 threads.
// Each thread: 4 adjacent columns (two packed f32x2 streams) x 8 rows.
// Tile col tc <-> img col bx + tc - 6. Compute reads tc[4..135] via LDS.128.
// Interior load: LDG.128 from img col bx-4 (16B aligned), quad q -> tc 4q+2,
// stored as two STS.64 (8B aligned). STRIDE 140 holds tc up to 137.
// Channels per row: H0=(h0,h1) H1=(h2,h3) H2=(h4,h5) (h_i = v_i+v_{i+1}+v_{i+2})
//                   C0=(v2,v3) C1=(v4,v5)
// Vertical: B(p)=H(p+2)+H(p+3)+H(p+4) fresh, A(p)=B(p-2) from a 2-slot pipe.
// ---------------------------------------------------------------------------
#define TX 128
#define TY 32
#define PY 8
#define TROWS 36
#define STRIDE 140

__global__ __launch_bounds__(128, 7) void swf_step_kernel(int srcIsA) {
    const float* __restrict__ src = (srcIsA ? g_bufA : g_bufB) + blockIdx.z * HW;
    float* __restrict__ dst       = (srcIsA ? g_bufB : g_bufA) + blockIdx.z * HW;

    __shared__ float tile[TROWS * STRIDE];

    const int tx = threadIdx.x, ty = threadIdx.y;
    const int bx = blockIdx.x * TX, by = blockIdx.y * TY;

    const bool interior = (blockIdx.x > 0) && (blockIdx.x < gridDim.x - 1) &&
                          (blockIdx.y > 0) && (blockIdx.y < gridDim.y - 1);

    if (interior) {
        // quad-granular: img cols [bx-4 .. bx+131] = 34 float4 per row
        const float* g = src + (by - 2) * IMG_W + (bx - 4);
        #pragma unroll
        for (int r = ty; r < TROWS; r += 4) {
            float4 v = *(const float4*)(g + r * IMG_W + 4 * tx);
            float* t = &tile[r * STRIDE + 4 * tx + 2];
            *(float2*)(t)     = make_float2(v.x, v.y);
            *(float2*)(t + 2) = make_float2(v.z, v.w);
            if (tx < 2) {
                float4 w = *(const float4*)(g + r * IMG_W + 128 + 4 * tx);
                float* t2 = &tile[r * STRIDE + 130 + 4 * tx];
                *(float2*)(t2)     = make_float2(w.x, w.y);
                *(float2*)(t2 + 2) = make_float2(w.z, w.w);
            }
        }
    } else {
        #pragma unroll
        for (int r = ty; r < TROWS; r += 4) {
            int gy = min(max(by + r - 2, 0), IMG_H - 1);
            const float* grow = src + gy * IMG_W;
            #pragma unroll
            for (int k = 0; k < 2; k++) {
                int idx = tx + 32 * k;
                int c0 = min(max(bx - 2 + 2 * idx, 0), IMG_W - 1);
                int c1 = min(max(bx - 1 + 2 * idx, 0), IMG_W - 1);
                *(float2*)&tile[r * STRIDE + 4 + 2 * idx] = make_float2(grow[c0], grow[c1]);
            }
            if (tx < 2) {
                int idx = tx + 64;
                int c0 = min(max(bx - 2 + 2 * idx, 0), IMG_W - 1);
                int c1 = min(max(bx - 1 + 2 * idx, 0), IMG_W - 1);
                *(float2*)&tile[r * STRIDE + 4 + 2 * idx] = make_float2(grow[c0], grow[c1]);
            }
        }
    }
    __syncthreads();

    const int row0 = ty * PY;

    auto loadrow = [&](int r, ull* o) {
        const float* base = &tile[r * STRIDE + 4 * tx + 4];
        float4 q0 = *(const float4*)(base);      // v0 v1 v2 v3
        float4 q1 = *(const float4*)(base + 4);  // v4 v5 v6 v7
        float s0 = q0.x + q0.y, s1 = q0.y + q0.z, s2 = q0.z + q0.w;
        float s3 = q0.w + q1.x, s4 = q1.x + q1.y, s5 = q1.y + q1.z;
        o[0] = pk(s0 + q0.z, s1 + q0.w);   // H0
        o[1] = pk(s2 + q1.x, s3 + q1.y);   // H1
        o[2] = pk(s4 + q1.z, s5 + q1.w);   // H2
        o[3] = pk(q0.z, q0.w);             // C0
        o[4] = pk(q1.x, q1.y);             // C1
    };

    const ull K9    = 0x4110000041100000ULL;  // ( 9, 9)
    const ull Km9   = 0xC1100000C1100000ULL;  // (-9,-9)
    const ull K15   = 0x4170000041700000ULL;  // (15,15)
    const ull Km135 = 0xC3070000C3070000ULL;  // (-135,-135)
    const float INV135 = 1.0f / 135.0f;

    // ---- prologue: rows 0..3 (tile-local). Ring slot = row_index % 3. ----
    ull R[3][5], Ap[2][5];
    {
        ull t0[5], t1[5];
        loadrow(row0 + 0, t0);
        loadrow(row0 + 1, t1);
        loadrow(row0 + 2, R[2]);   // row 2 -> slot 2
        loadrow(row0 + 3, R[0]);   // row 3 -> slot 0
        #pragma unroll
        for (int ch = 0; ch < 5; ch++) {
            ull s = add2(t1[ch], R[2][ch]);
            Ap[0][ch] = add2(t0[ch], s);        // V(0..2) = A(0)
            Ap[1][ch] = add2(s, R[0][ch]);      // V(1..3) = A(1)
        }
    }

    float* drow = dst + (by + row0) * IMG_W + bx + 4 * tx;

    #pragma unroll
    for (int p = 0; p < PY; p++) {
        const int snew = (p + 4) % 3;   // incoming row p+4
        const int smid = (p + 2) % 3;   // middle row p+2
        const int s3   = (p + 3) % 3;   // row p+3

        loadrow(row0 + p + 4, R[snew]);

        ull B[5];
        #pragma unroll
        for (int ch = 0; ch < 5; ch++)
            B[ch] = add2(add2(R[smid][ch], R[s3][ch]), R[snew][ch]);  // V(p+2..p+4)

        const ull* A = Ap[p & 1];
        const ull* M = R[smid];

        // shared window sums across both streams
        ull AB0 = add2(A[0], B[0]);
        ull AB1 = add2(A[1], B[1]);
        ull AB2 = add2(A[2], B[2]);
        ull A01 = add2(A[0], A[1]);
        ull A12 = add2(A[1], A[2]);
        ull B01 = add2(B[0], B[1]);
        ull B12 = add2(B[1], B[2]);

        float4 outv;

        {   // stream 0: cols c0,c1  (Hl=H0, Hr=H1, cc=C0)
            ull negC = mul2(M[3], Km135);
            ull eL  = fma2(M[0], Km9, fma2(AB0, K9, negC));
            ull eR  = fma2(M[1], Km9, fma2(AB1, K9, negC));
            ull eU  = fma2(A[3], Km9, fma2(A01, K9, negC));
            ull eD  = fma2(B[3], Km9, fma2(B01, K9, negC));
            ull eNW = fma2(A[0], K15, negC);
            ull eNE = fma2(A[1], K15, negC);
            ull eSW = fma2(B[0], K15, negC);
            ull eSE = fma2(B[1], K15, negC);

            float c0, c1;   upk(M[3], c0, c1);
            float l0, l1;   upk(eL,  l0, l1);
            float r0, r1;   upk(eR,  r0, r1);
            float u0, u1;   upk(eU,  u0, u1);
            float d0, d1;   upk(eD,  d0, d1);
            float nw0, nw1; upk(eNW, nw0, nw1);
            float ne0, ne1; upk(eNE, ne0, ne1);
            float sw0, sw1; upk(eSW, sw0, sw1);
            float se0, se1; upk(eSE, se0, se1);

            float m0 = selmin(selmin(selmin(l0, r0), selmin(u0, d0)),
                              selmin(selmin(nw0, ne0), selmin(sw0, se0)));
            float m1 = selmin(selmin(selmin(l1, r1), selmin(u1, d1)),
                              selmin(selmin(nw1, ne1), selmin(sw1, se1)));
            outv.x = fmaf(m0, INV135, c0);
            outv.y = fmaf(m1, INV135, c1);
        }
        {   // stream 1: cols c2,c3  (Hl=H1, Hr=H2, cc=C1)
            ull negC = mul2(M[4], Km135);
            ull eL  = fma2(M[1], Km9, fma2(AB1, K9, negC));
            ull eR  = fma2(M[2], Km9, fma2(AB2, K9, negC));
            ull eU  = fma2(A[4], Km9, fma2(A12, K9, negC));
            ull eD  = fma2(B[4], Km9, fma2(B12, K9, negC));
            ull eNW = fma2(A[1], K15, negC);
            ull eNE = fma2(A[2], K15, negC);
            ull eSW = fma2(B[1], K15, negC);
            ull eSE = fma2(B[2], K15, negC);

            float c0, c1;   upk(M[4], c0, c1);
            float l0, l1;   upk(eL,  l0, l1);
            float r0, r1;   upk(eR,  r0, r1);
            float u0, u1;   upk(eU,  u0, u1);
            float d0, d1;   upk(eD,  d0, d1);
            float nw0, nw1; upk(eNW, nw0, nw1);
            float ne0, ne1; upk(eNE, ne0, ne1);
            float sw0, sw1; upk(eSW, sw0, sw1);
            float se0, se1; upk(eSE, se0, se1);

            float m0 = selmin(selmin(selmin(l0, r0), selmin(u0, d0)),
                              selmin(selmin(nw0, ne0), selmin(sw0, se0)));
            float m1 = selmin(selmin(selmin(l1, r1), selmin(u1, d1)),
                              selmin(selmin(nw1, ne1), selmin(sw1, se1)));
            outv.z = fmaf(m0, INV135, c0);
            outv.w = fmaf(m1, INV135, c1);
        }

        *(float4*)drow = outv;
        drow += IMG_W;

        #pragma unroll
        for (int ch = 0; ch < 5; ch++) Ap[p & 1][ch] = B[ch];  // A(p+2) = B(p)
    }
}

// ---------------------------------------------------------------------------
// |x0 - res| clipped, CHW -> HWC (float4-vectorized, 4 pixels/thread)
// ---------------------------------------------------------------------------
__global__ void finalize_kernel(const float* __restrict__ img, float* __restrict__ out) {
    int p = blockIdx.x * blockDim.x + threadIdx.x;
    if (p >= HW / 4) return;
    const float4* in = (const float4*)img + 3 * p;
    float4 a = in[0], b = in[1], c = in[2];
    float4 r0 = ((const float4*)(g_bufA + 0 * HW))[p];
    float4 r1 = ((const float4*)(g_bufA + 1 * HW))[p];
    float4 r2 = ((const float4*)(g_bufA + 2 * HW))[p];
    float4 o0 = make_float4(fminf(fabsf(a.x - r0.x), 255.f), fminf(fabsf(a.y - r1.x), 255.f),
                            fminf(fabsf(a.z - r2.x), 255.f), fminf(fabsf(a.w - r0.y), 255.f));
    float4 o1 = make_float4(fminf(fabsf(b.x - r1.y), 255.f), fminf(fabsf(b.y - r2.y), 255.f),
                            fminf(fabsf(b.z - r0.z), 255.f), fminf(fabsf(b.w - r1.z), 255.f));
    float4 o2 = make_float4(fminf(fabsf(c.x - r2.z), 255.f), fminf(fabsf(c.y - r0.w), 255.f),
                            fminf(fabsf(c.z - r1.w), 255.f), fminf(fabsf(c.w - r2.w), 255.f));
    float4* op = (float4*)out + 3 * p;
    op[0] = o0; op[1] = o1; op[2] = o2;
}

// ---------------------------------------------------------------------------
extern "C" void kernel_launch(void* const* d_in, const int* in_sizes, int n_in,
                              void* d_out, int out_size) {
    const float* img = (const float*)d_in[0];
    float* out = (float*)d_out;

    hwc2chw_kernel<<<HW / 4 / 256, 256>>>(img);

    dim3 grid(IMG_W / TX, IMG_H / TY, NCH);
    dim3 block(32, 4);
    for (int it = 0; it < ITER; it++) {
        swf_step_kernel<<<grid, block>>>((it & 1) == 0 ? 1 : 0);
    }
    // After 8 iterations (even), result is back in g_bufA.
    finalize_kernel<<<HW / 4 / 256, 256>>>(img, out);
}

// round 12
// speedup vs baseline: 1.5323x; 1.1263x over previous
#include <cuda_runtime.h>
#include <cstdint>

#define IMG_H 2048
#define IMG_W 2048
#define HW (IMG_H * IMG_W)
#define NCH 3
#define ITER 8

// Ping-pong scratch planes (CHW, planar). Device globals: allowed scratch.
__device__ float g_bufA[NCH * HW];
__device__ float g_bufB[NCH * HW];

typedef unsigned long long ull;
typedef unsigned int u32;

// ---------------- packed f32x2 helpers (Blackwell dual-FP32) ----------------
__device__ __forceinline__ ull pk(float lo, float hi) {
    ull r; asm("mov.b64 %0, {%1, %2};" : "=l"(r) : "f"(lo), "f"(hi)); return r;
}
__device__ __forceinline__ void upk(ull v, float& lo, float& hi) {
    asm("mov.b64 {%0, %1}, %2;" : "=f"(lo), "=f"(hi) : "l"(v));
}
__device__ __forceinline__ ull add2(ull a, ull b) {
    ull r; asm("add.rn.f32x2 %0, %1, %2;" : "=l"(r) : "l"(a), "l"(b)); return r;
}
__device__ __forceinline__ ull mul2(ull a, ull b) {
    ull r; asm("mul.rn.f32x2 %0, %1, %2;" : "=l"(r) : "l"(a), "l"(b)); return r;
}
__device__ __forceinline__ ull fma2(ull a, ull b, ull c) {
    ull r; asm("fma.rn.f32x2 %0, %1, %2, %3;" : "=l"(r) : "l"(a), "l"(b), "l"(c)); return r;
}
// keep `a` on tie (earlier kernel has priority) -> FSETP(|.|)+FSEL, 2 ops
__device__ __forceinline__ float selmin(float a, float b) {
    return (fabsf(b) < fabsf(a)) ? b : a;
}
// fire-and-forget 8-byte global->shared copy (LDGSTS)
__device__ __forceinline__ void cpa8(u32 smem_dst, const float* gsrc) {
    asm volatile("cp.async.ca.shared.global [%0], [%1], 8;\n"
                 :: "r"(smem_dst), "l"(gsrc) : "memory");
}

// ---------------------------------------------------------------------------
// HWC -> CHW planar (float4-vectorized, 4 pixels/thread)
// ---------------------------------------------------------------------------
__global__ void hwc2chw_kernel(const float* __restrict__ img) {
    int p = blockIdx.x * blockDim.x + threadIdx.x;
    if (p >= HW / 4) return;
    const float4* in = (const float4*)img + 3 * p;
    float4 a = in[0], b = in[1], c = in[2];
    ((float4*)(g_bufA + 0 * HW))[p] = make_float4(a.x, a.w, b.z, c.y);
    ((float4*)(g_bufA + 1 * HW))[p] = make_float4(a.y, b.x, b.w, c.z);
    ((float4*)(g_bufA + 2 * HW))[p] = make_float4(a.z, b.y, c.x, c.w);
}

// ---------------------------------------------------------------------------
// One SWF iteration. Tile: 128 wide x 32 high per block (32,4)=128 threads.
// Each thread: 4 adjacent columns (two packed f32x2 streams) x 8 rows.
// Channels per row: H0=(h0,h1) H1=(h2,h3) H2=(h4,h5) (h_i = v_i+v_{i+1}+v_{i+2})
//                   C0=(v2,v3) C1=(v4,v5)
// Vertical: B(p)=H(p+2)+H(p+3)+H(p+4) fresh, A(p)=B(p-2) from a 2-slot pipe.
// Interior tile load uses cp.async (LDGSTS): no LDG->STS register dependency.
// ---------------------------------------------------------------------------
#define TX 128
#define TY 32
#define PY 8
#define TROWS 36
#define STRIDE 136

__global__ __launch_bounds__(128, 7) void swf_step_kernel(int srcIsA) {
    const float* __restrict__ src = (srcIsA ? g_bufA : g_bufB) + blockIdx.z * HW;
    float* __restrict__ dst       = (srcIsA ? g_bufB : g_bufA) + blockIdx.z * HW;

    __shared__ float tile[TROWS * STRIDE];

    const int tx = threadIdx.x, ty = threadIdx.y;
    const int bx = blockIdx.x * TX, by = blockIdx.y * TY;

    const bool interior = (blockIdx.x > 0) && (blockIdx.x < gridDim.x - 1) &&
                          (blockIdx.y > 0) && (blockIdx.y < gridDim.y - 1);

    if (interior) {
        const float* g = src + (by - 2) * IMG_W + (bx - 2) + 2 * tx;
        u32 td = (u32)__cvta_generic_to_shared(tile) + (4 + 2 * tx) * 4;
        #pragma unroll
        for (int r = ty; r < TROWS; r += 4) {
            cpa8(td + r * (STRIDE * 4),       g + r * IMG_W);
            cpa8(td + r * (STRIDE * 4) + 256, g + r * IMG_W + 64);
            if (tx < 2)
                cpa8(td + r * (STRIDE * 4) + 512, g + r * IMG_W + 128);
        }
        asm volatile("cp.async.commit_group;\n" ::: "memory");
        asm volatile("cp.async.wait_group 0;\n" ::: "memory");
    } else {
        #pragma unroll
        for (int r = ty; r < TROWS; r += 4) {
            int gy = min(max(by + r - 2, 0), IMG_H - 1);
            const float* grow = src + gy * IMG_W;
            #pragma unroll
            for (int k = 0; k < 2; k++) {
                int idx = tx + 32 * k;
                int c0 = min(max(bx - 2 + 2 * idx, 0), IMG_W - 1);
                int c1 = min(max(bx - 1 + 2 * idx, 0), IMG_W - 1);
                *(float2*)&tile[r * STRIDE + 4 + 2 * idx] = make_float2(grow[c0], grow[c1]);
            }
            if (tx < 2) {
                int idx = tx + 64;
                int c0 = min(max(bx - 2 + 2 * idx, 0), IMG_W - 1);
                int c1 = min(max(bx - 1 + 2 * idx, 0), IMG_W - 1);
                *(float2*)&tile[r * STRIDE + 4 + 2 * idx] = make_float2(grow[c0], grow[c1]);
            }
        }
    }
    __syncthreads();

    const int row0 = ty * PY;

    auto loadrow = [&](int r, ull* o) {
        const float* base = &tile[r * STRIDE + 4 * tx + 4];
        float4 q0 = *(const float4*)(base);      // v0 v1 v2 v3
        float4 q1 = *(const float4*)(base + 4);  // v4 v5 v6 v7
        float s0 = q0.x + q0.y, s1 = q0.y + q0.z, s2 = q0.z + q0.w;
        float s3 = q0.w + q1.x, s4 = q1.x + q1.y, s5 = q1.y + q1.z;
        o[0] = pk(s0 + q0.z, s1 + q0.w);   // H0
        o[1] = pk(s2 + q1.x, s3 + q1.y);   // H1
        o[2] = pk(s4 + q1.z, s5 + q1.w);   // H2
        o[3] = pk(q0.z, q0.w);             // C0
        o[4] = pk(q1.x, q1.y);             // C1
    };

    const ull K9    = 0x4110000041100000ULL;  // ( 9, 9)
    const ull Km9   = 0xC1100000C1100000ULL;  // (-9,-9)
    const ull K15   = 0x4170000041700000ULL;  // (15,15)
    const ull Km135 = 0xC3070000C3070000ULL;  // (-135,-135)
    const float INV135 = 1.0f / 135.0f;

    // ---- prologue: rows 0..3 (tile-local). Ring slot = row_index % 3. ----
    ull R[3][5], Ap[2][5];
    {
        ull t0[5], t1[5];
        loadrow(row0 + 0, t0);
        loadrow(row0 + 1, t1);
        loadrow(row0 + 2, R[2]);   // row 2 -> slot 2
        loadrow(row0 + 3, R[0]);   // row 3 -> slot 0
        #pragma unroll
        for (int ch = 0; ch < 5; ch++) {
            ull s = add2(t1[ch], R[2][ch]);
            Ap[0][ch] = add2(t0[ch], s);        // V(0..2) = A(0)
            Ap[1][ch] = add2(s, R[0][ch]);      // V(1..3) = A(1)
        }
    }

    float* drow = dst + (by + row0) * IMG_W + bx + 4 * tx;

    #pragma unroll
    for (int p = 0; p < PY; p++) {
        const int snew = (p + 4) % 3;   // incoming row p+4
        const int smid = (p + 2) % 3;   // middle row p+2
        const int s3   = (p + 3) % 3;   // row p+3

        loadrow(row0 + p + 4, R[snew]);

        ull B[5];
        #pragma unroll
        for (int ch = 0; ch < 5; ch++)
            B[ch] = add2(add2(R[smid][ch], R[s3][ch]), R[snew][ch]);  // V(p+2..p+4)

        const ull* A = Ap[p & 1];
        const ull* M = R[smid];

        // shared window sums across both streams
        ull AB0 = add2(A[0], B[0]);
        ull AB1 = add2(A[1], B[1]);
        ull AB2 = add2(A[2], B[2]);
        ull A01 = add2(A[0], A[1]);
        ull A12 = add2(A[1], A[2]);
        ull B01 = add2(B[0], B[1]);
        ull B12 = add2(B[1], B[2]);

        float4 outv;

        {   // stream 0: cols c0,c1  (Hl=H0, Hr=H1, cc=C0)
            ull negC = mul2(M[3], Km135);
            ull eL  = fma2(M[0], Km9, fma2(AB0, K9, negC));
            ull eR  = fma2(M[1], Km9, fma2(AB1, K9, negC));
            ull eU  = fma2(A[3], Km9, fma2(A01, K9, negC));
            ull eD  = fma2(B[3], Km9, fma2(B01, K9, negC));
            ull eNW = fma2(A[0], K15, negC);
            ull eNE = fma2(A[1], K15, negC);
            ull eSW = fma2(B[0], K15, negC);
            ull eSE = fma2(B[1], K15, negC);

            float c0, c1;   upk(M[3], c0, c1);
            float l0, l1;   upk(eL,  l0, l1);
            float r0, r1;   upk(eR,  r0, r1);
            float u0, u1;   upk(eU,  u0, u1);
            float d0, d1;   upk(eD,  d0, d1);
            float nw0, nw1; upk(eNW, nw0, nw1);
            float ne0, ne1; upk(eNE, ne0, ne1);
            float sw0, sw1; upk(eSW, sw0, sw1);
            float se0, se1; upk(eSE, se0, se1);

            float m0 = selmin(selmin(selmin(l0, r0), selmin(u0, d0)),
                              selmin(selmin(nw0, ne0), selmin(sw0, se0)));
            float m1 = selmin(selmin(selmin(l1, r1), selmin(u1, d1)),
                              selmin(selmin(nw1, ne1), selmin(sw1, se1)));
            outv.x = fmaf(m0, INV135, c0);
            outv.y = fmaf(m1, INV135, c1);
        }
        {   // stream 1: cols c2,c3  (Hl=H1, Hr=H2, cc=C1)
            ull negC = mul2(M[4], Km135);
            ull eL  = fma2(M[1], Km9, fma2(AB1, K9, negC));
            ull eR  = fma2(M[2], Km9, fma2(AB2, K9, negC));
            ull eU  = fma2(A[4], Km9, fma2(A12, K9, negC));
            ull eD  = fma2(B[4], Km9, fma2(B12, K9, negC));
            ull eNW = fma2(A[1], K15, negC);
            ull eNE = fma2(A[2], K15, negC);
            ull eSW = fma2(B[1], K15, negC);
            ull eSE = fma2(B[2], K15, negC);

            float c0, c1;   upk(M[4], c0, c1);
            float l0, l1;   upk(eL,  l0, l1);
            float r0, r1;   upk(eR,  r0, r1);
            float u0, u1;   upk(eU,  u0, u1);
            float d0, d1;   upk(eD,  d0, d1);
            float nw0, nw1; upk(eNW, nw0, nw1);
            float ne0, ne1; upk(eNE, ne0, ne1);
            float sw0, sw1; upk(eSW, sw0, sw1);
            float se0, se1; upk(eSE, se0, se1);

            float m0 = selmin(selmin(selmin(l0, r0), selmin(u0, d0)),
                              selmin(selmin(nw0, ne0), selmin(sw0, se0)));
            float m1 = selmin(selmin(selmin(l1, r1), selmin(u1, d1)),
                              selmin(selmin(nw1, ne1), selmin(sw1, se1)));
            outv.z = fmaf(m0, INV135, c0);
            outv.w = fmaf(m1, INV135, c1);
        }

        *(float4*)drow = outv;
        drow += IMG_W;

        #pragma unroll
        for (int ch = 0; ch < 5; ch++) Ap[p & 1][ch] = B[ch];  // A(p+2) = B(p)
    }
}

// ---------------------------------------------------------------------------
// |x0 - res| clipped, CHW -> HWC (float4-vectorized, 4 pixels/thread)
// ---------------------------------------------------------------------------
__global__ void finalize_kernel(const float* __restrict__ img, float* __restrict__ out) {
    int p = blockIdx.x * blockDim.x + threadIdx.x;
    if (p >= HW / 4) return;
    const float4* in = (const float4*)img + 3 * p;
    float4 a = in[0], b = in[1], c = in[2];
    float4 r0 = ((const float4*)(g_bufA + 0 * HW))[p];
    float4 r1 = ((const float4*)(g_bufA + 1 * HW))[p];
    float4 r2 = ((const float4*)(g_bufA + 2 * HW))[p];
    float4 o0 = make_float4(fminf(fabsf(a.x - r0.x), 255.f), fminf(fabsf(a.y - r1.x), 255.f),
                            fminf(fabsf(a.z - r2.x), 255.f), fminf(fabsf(a.w - r0.y), 255.f));
    float4 o1 = make_float4(fminf(fabsf(b.x - r1.y), 255.f), fminf(fabsf(b.y - r2.y), 255.f),
                            fminf(fabsf(b.z - r0.z), 255.f), fminf(fabsf(b.w - r1.z), 255.f));
    float4 o2 = make_float4(fminf(fabsf(c.x - r2.z), 255.f), fminf(fabsf(c.y - r0.w), 255.f),
                            fminf(fabsf(c.z - r1.w), 255.f), fminf(fabsf(c.w - r2.w), 255.f));
    float4* op = (float4*)out + 3 * p;
    op[0] = o0; op[1] = o1; op[2] = o2;
}

// ---------------------------------------------------------------------------
extern "C" void kernel_launch(void* const* d_in, const int* in_sizes, int n_in,
                              void* d_out, int out_size) {
    const float* img = (const float*)d_in[0];
    float* out = (float*)d_out;

    hwc2chw_kernel<<<HW / 4 / 256, 256>>>(img);

    dim3 grid(IMG_W / TX, IMG_H / TY, NCH);
    dim3 block(32, 4);
    for (int it = 0; it < ITER; it++) {
        swf_step_kernel<<<grid, block>>>((it & 1) == 0 ? 1 : 0);
    }
    // After 8 iterations (even), result is back in g_bufA.
    finalize_kernel<<<HW / 4 / 256, 256>>>(img, out);
}

// round 13
// speedup vs baseline: 1.6079x; 1.0494x over previous
#include <cuda_runtime.h>
#include <cstdint>

#define IMG_H 2048
#define IMG_W 2048
#define HW (IMG_H * IMG_W)
#define NCH 3
#define ITER 8

// Ping-pong scratch planes (CHW, planar). Device globals: allowed scratch.
__device__ float g_bufA[NCH * HW];
__device__ float g_bufB[NCH * HW];

typedef unsigned long long ull;
typedef unsigned int u32;

// ---------------- packed f32x2 helpers (Blackwell dual-FP32) ----------------
__device__ __forceinline__ ull pk(float lo, float hi) {
    ull r; asm("mov.b64 %0, {%1, %2};" : "=l"(r) : "f"(lo), "f"(hi)); return r;
}
__device__ __forceinline__ void upk(ull v, float& lo, float& hi) {
    asm("mov.b64 {%0, %1}, %2;" : "=f"(lo), "=f"(hi) : "l"(v));
}
__device__ __forceinline__ ull add2(ull a, ull b) {
    ull r; asm("add.rn.f32x2 %0, %1, %2;" : "=l"(r) : "l"(a), "l"(b)); return r;
}
__device__ __forceinline__ ull mul2(ull a, ull b) {
    ull r; asm("mul.rn.f32x2 %0, %1, %2;" : "=l"(r) : "l"(a), "l"(b)); return r;
}
__device__ __forceinline__ ull fma2(ull a, ull b, ull c) {
    ull r; asm("fma.rn.f32x2 %0, %1, %2, %3;" : "=l"(r) : "l"(a), "l"(b), "l"(c)); return r;
}
// keep `a` on tie (earlier kernel has priority) -> FSETP(|.|)+FSEL, 2 ops
__device__ __forceinline__ float selmin(float a, float b) {
    return (fabsf(b) < fabsf(a)) ? b : a;
}
// fire-and-forget 8-byte global->shared copy (LDGSTS)
__device__ __forceinline__ void cpa8(u32 smem_dst, const float* gsrc) {
    asm volatile("cp.async.ca.shared.global [%0], [%1], 8;\n"
                 :: "r"(smem_dst), "l"(gsrc) : "memory");
}

// ---------------------------------------------------------------------------
// HWC -> CHW planar (float4-vectorized, 4 pixels/thread)
// ---------------------------------------------------------------------------
__global__ void hwc2chw_kernel(const float* __restrict__ img) {
    int p = blockIdx.x * blockDim.x + threadIdx.x;
    if (p >= HW / 4) return;
    const float4* in = (const float4*)img + 3 * p;
    float4 a = in[0], b = in[1], c = in[2];
    ((float4*)(g_bufA + 0 * HW))[p] = make_float4(a.x, a.w, b.z, c.y);
    ((float4*)(g_bufA + 1 * HW))[p] = make_float4(a.y, b.x, b.w, c.z);
    ((float4*)(g_bufA + 2 * HW))[p] = make_float4(a.z, b.y, c.x, c.w);
}

// ---------------------------------------------------------------------------
// One SWF iteration. Tile: 128 wide x 32 high per block (32,4)=128 threads.
// Each WARP owns an 8-row output strip and a PRIVATE smem buffer of its 12
// input rows (8 + 4 halo). No __syncthreads(): cp.async + wait + __syncwarp.
// Each thread: 4 adjacent columns (two packed f32x2 streams) x 8 rows.
// Channels per row: H0=(h0,h1) H1=(h2,h3) H2=(h4,h5) (h_i = v_i+v_{i+1}+v_{i+2})
//                   C0=(v2,v3) C1=(v4,v5)
// Vertical: B(p)=H(p+2)+H(p+3)+H(p+4) fresh, A(p)=B(p-2) from a 2-slot pipe.
// ---------------------------------------------------------------------------
#define TX 128
#define TY 32
#define PY 8
#define WROWS 12
#define STRIDE 136

__global__ __launch_bounds__(128, 7) void swf_step_kernel(int srcIsA) {
    const float* __restrict__ src = (srcIsA ? g_bufA : g_bufB) + blockIdx.z * HW;
    float* __restrict__ dst       = (srcIsA ? g_bufB : g_bufA) + blockIdx.z * HW;

    __shared__ float tile[4 * WROWS * STRIDE];

    const int tx = threadIdx.x, ty = threadIdx.y;
    const int bx = blockIdx.x * TX, by = blockIdx.y * TY;
    float* wtile = tile + ty * (WROWS * STRIDE);   // this warp's private buffer
    const int wrow0 = by + ty * PY - 2;            // global row of wtile row 0

    const bool interior = (blockIdx.x > 0) && (blockIdx.x < gridDim.x - 1) &&
                          (blockIdx.y > 0) && (blockIdx.y < gridDim.y - 1);

    if (interior) {
        const float* g = src + wrow0 * IMG_W + (bx - 2) + 2 * tx;
        u32 td = (u32)__cvta_generic_to_shared(wtile) + (4 + 2 * tx) * 4;
        #pragma unroll
        for (int r = 0; r < WROWS; r++) {
            cpa8(td + r * (STRIDE * 4),       g + r * IMG_W);
            cpa8(td + r * (STRIDE * 4) + 256, g + r * IMG_W + 64);
            if (tx < 2)
                cpa8(td + r * (STRIDE * 4) + 512, g + r * IMG_W + 128);
        }
        asm volatile("cp.async.commit_group;\n" ::: "memory");
        asm volatile("cp.async.wait_group 0;\n" ::: "memory");
        __syncwarp();
    } else {
        #pragma unroll
        for (int r = 0; r < WROWS; r++) {
            int gy = min(max(wrow0 + r, 0), IMG_H - 1);
            const float* grow = src + gy * IMG_W;
            #pragma unroll
            for (int k = 0; k < 2; k++) {
                int idx = tx + 32 * k;
                int c0 = min(max(bx - 2 + 2 * idx, 0), IMG_W - 1);
                int c1 = min(max(bx - 1 + 2 * idx, 0), IMG_W - 1);
                *(float2*)&wtile[r * STRIDE + 4 + 2 * idx] = make_float2(grow[c0], grow[c1]);
            }
            if (tx < 2) {
                int idx = tx + 64;
                int c0 = min(max(bx - 2 + 2 * idx, 0), IMG_W - 1);
                int c1 = min(max(bx - 1 + 2 * idx, 0), IMG_W - 1);
                *(float2*)&wtile[r * STRIDE + 4 + 2 * idx] = make_float2(grow[c0], grow[c1]);
            }
        }
        __syncwarp();
    }

    auto loadrow = [&](int r, ull* o) {
        const float* base = &wtile[r * STRIDE + 4 * tx + 4];
        float4 q0 = *(const float4*)(base);      // v0 v1 v2 v3
        float4 q1 = *(const float4*)(base + 4);  // v4 v5 v6 v7
        float s0 = q0.x + q0.y, s1 = q0.y + q0.z, s2 = q0.z + q0.w;
        float s3 = q0.w + q1.x, s4 = q1.x + q1.y, s5 = q1.y + q1.z;
        o[0] = pk(s0 + q0.z, s1 + q0.w);   // H0
        o[1] = pk(s2 + q1.x, s3 + q1.y);   // H1
        o[2] = pk(s4 + q1.z, s5 + q1.w);   // H2
        o[3] = pk(q0.z, q0.w);             // C0
        o[4] = pk(q1.x, q1.y);             // C1
    };

    const ull K9    = 0x4110000041100000ULL;  // ( 9, 9)
    const ull Km9   = 0xC1100000C1100000ULL;  // (-9,-9)
    const ull K15   = 0x4170000041700000ULL;  // (15,15)
    const ull Km135 = 0xC3070000C3070000ULL;  // (-135,-135)
    const float INV135 = 1.0f / 135.0f;

    // ---- prologue: strip rows 0..3 (wtile-local). Ring slot = row % 3. ----
    ull R[3][5], Ap[2][5];
    {
        ull t0[5], t1[5];
        loadrow(0, t0);
        loadrow(1, t1);
        loadrow(2, R[2]);   // row 2 -> slot 2
        loadrow(3, R[0]);   // row 3 -> slot 0
        #pragma unroll
        for (int ch = 0; ch < 5; ch++) {
            ull s = add2(t1[ch], R[2][ch]);
            Ap[0][ch] = add2(t0[ch], s);        // V(0..2) = A(0)
            Ap[1][ch] = add2(s, R[0][ch]);      // V(1..3) = A(1)
        }
    }

    float* drow = dst + (by + ty * PY) * IMG_W + bx + 4 * tx;

    #pragma unroll
    for (int p = 0; p < PY; p++) {
        const int snew = (p + 4) % 3;   // incoming row p+4
        const int smid = (p + 2) % 3;   // middle row p+2
        const int s3   = (p + 3) % 3;   // row p+3

        loadrow(p + 4, R[snew]);

        ull B[5];
        #pragma unroll
        for (int ch = 0; ch < 5; ch++)
            B[ch] = add2(add2(R[smid][ch], R[s3][ch]), R[snew][ch]);  // V(p+2..p+4)

        const ull* A = Ap[p & 1];
        const ull* M = R[smid];

        // shared window sums across both streams
        ull AB0 = add2(A[0], B[0]);
        ull AB1 = add2(A[1], B[1]);
        ull AB2 = add2(A[2], B[2]);
        ull A01 = add2(A[0], A[1]);
        ull A12 = add2(A[1], A[2]);
        ull B01 = add2(B[0], B[1]);
        ull B12 = add2(B[1], B[2]);

        float4 outv;

        {   // stream 0: cols c0,c1  (Hl=H0, Hr=H1, cc=C0)
            ull negC = mul2(M[3], Km135);
            ull eL  = fma2(M[0], Km9, fma2(AB0, K9, negC));
            ull eR  = fma2(M[1], Km9, fma2(AB1, K9, negC));
            ull eU  = fma2(A[3], Km9, fma2(A01, K9, negC));
            ull eD  = fma2(B[3], Km9, fma2(B01, K9, negC));
            ull eNW = fma2(A[0], K15, negC);
            ull eNE = fma2(A[1], K15, negC);
            ull eSW = fma2(B[0], K15, negC);
            ull eSE = fma2(B[1], K15, negC);

            float c0, c1;   upk(M[3], c0, c1);
            float l0, l1;   upk(eL,  l0, l1);
            float r0, r1;   upk(eR,  r0, r1);
            float u0, u1;   upk(eU,  u0, u1);
            float d0, d1;   upk(eD,  d0, d1);
            float nw0, nw1; upk(eNW, nw0, nw1);
            float ne0, ne1; upk(eNE, ne0, ne1);
            float sw0, sw1; upk(eSW, sw0, sw1);
            float se0, se1; upk(eSE, se0, se1);

            float m0 = selmin(selmin(selmin(l0, r0), selmin(u0, d0)),
                              selmin(selmin(nw0, ne0), selmin(sw0, se0)));
            float m1 = selmin(selmin(selmin(l1, r1), selmin(u1, d1)),
                              selmin(selmin(nw1, ne1), selmin(sw1, se1)));
            outv.x = fmaf(m0, INV135, c0);
            outv.y = fmaf(m1, INV135, c1);
        }
        {   // stream 1: cols c2,c3  (Hl=H1, Hr=H2, cc=C1)
            ull negC = mul2(M[4], Km135);
            ull eL  = fma2(M[1], Km9, fma2(AB1, K9, negC));
            ull eR  = fma2(M[2], Km9, fma2(AB2, K9, negC));
            ull eU  = fma2(A[4], Km9, fma2(A12, K9, negC));
            ull eD  = fma2(B[4], Km9, fma2(B12, K9, negC));
            ull eNW = fma2(A[1], K15, negC);
            ull eNE = fma2(A[2], K15, negC);
            ull eSW = fma2(B[1], K15, negC);
            ull eSE = fma2(B[2], K15, negC);

            float c0, c1;   upk(M[4], c0, c1);
            float l0, l1;   upk(eL,  l0, l1);
            float r0, r1;   upk(eR,  r0, r1);
            float u0, u1;   upk(eU,  u0, u1);
            float d0, d1;   upk(eD,  d0, d1);
            float nw0, nw1; upk(eNW, nw0, nw1);
            float ne0, ne1; upk(eNE, ne0, ne1);
            float sw0, sw1; upk(eSW, sw0, sw1);
            float se0, se1; upk(eSE, se0, se1);

            float m0 = selmin(selmin(selmin(l0, r0), selmin(u0, d0)),
                              selmin(selmin(nw0, ne0), selmin(sw0, se0)));
            float m1 = selmin(selmin(selmin(l1, r1), selmin(u1, d1)),
                              selmin(selmin(nw1, ne1), selmin(sw1, se1)));
            outv.z = fmaf(m0, INV135, c0);
            outv.w = fmaf(m1, INV135, c1);
        }

        *(float4*)drow = outv;
        drow += IMG_W;

        #pragma unroll
        for (int ch = 0; ch < 5; ch++) Ap[p & 1][ch] = B[ch];  // A(p+2) = B(p)
    }
}

// ---------------------------------------------------------------------------
// |x0 - res| clipped, CHW -> HWC (float4-vectorized, 4 pixels/thread)
// ---------------------------------------------------------------------------
__global__ void finalize_kernel(const float* __restrict__ img, float* __restrict__ out) {
    int p = blockIdx.x * blockDim.x + threadIdx.x;
    if (p >= HW / 4) return;
    const float4* in = (const float4*)img + 3 * p;
    float4 a = in[0], b = in[1], c = in[2];
    float4 r0 = ((const float4*)(g_bufA + 0 * HW))[p];
    float4 r1 = ((const float4*)(g_bufA + 1 * HW))[p];
    float4 r2 = ((const float4*)(g_bufA + 2 * HW))[p];
    float4 o0 = make_float4(fminf(fabsf(a.x - r0.x), 255.f), fminf(fabsf(a.y - r1.x), 255.f),
                            fminf(fabsf(a.z - r2.x), 255.f), fminf(fabsf(a.w - r0.y), 255.f));
    float4 o1 = make_float4(fminf(fabsf(b.x - r1.y), 255.f), fminf(fabsf(b.y - r2.y), 255.f),
                            fminf(fabsf(b.z - r0.z), 255.f), fminf(fabsf(b.w - r1.z), 255.f));
    float4 o2 = make_float4(fminf(fabsf(c.x - r2.z), 255.f), fminf(fabsf(c.y - r0.w), 255.f),
                            fminf(fabsf(c.z - r1.w), 255.f), fminf(fabsf(c.w - r2.w), 255.f));
    float4* op = (float4*)out + 3 * p;
    op[0] = o0; op[1] = o1; op[2] = o2;
}

// ---------------------------------------------------------------------------
extern "C" void kernel_launch(void* const* d_in, const int* in_sizes, int n_in,
                              void* d_out, int out_size) {
    const float* img = (const float*)d_in[0];
    float* out = (float*)d_out;

    hwc2chw_kernel<<<HW / 4 / 256, 256>>>(img);

    dim3 grid(IMG_W / TX, IMG_H / TY, NCH);
    dim3 block(32, 4);
    for (int it = 0; it < ITER; it++) {
        swf_step_kernel<<<grid, block>>>((it & 1) == 0 ? 1 : 0);
    }
    // After 8 iterations (even), result is back in g_bufA.
    finalize_kernel<<<HW / 4 / 256, 256>>>(img, out);
}

// round 14
// speedup vs baseline: 1.6963x; 1.0549x over previous
#include <cuda_runtime.h>
#include <cstdint>

#define IMG_H 2048
#define IMG_W 2048
#define HW (IMG_H * IMG_W)
#define NCH 3
#define ITER 8

// Ping-pong scratch planes (CHW, planar). Device globals: allowed scratch.
__device__ float g_bufA[NCH * HW];
__device__ float g_bufB[NCH * HW];

typedef unsigned long long ull;
typedef unsigned int u32;

// ---------------- packed f32x2 helpers (Blackwell dual-FP32) ----------------
__device__ __forceinline__ ull pk(float lo, float hi) {
    ull r; asm("mov.b64 %0, {%1, %2};" : "=l"(r) : "f"(lo), "f"(hi)); return r;
}
__device__ __forceinline__ void upk(ull v, float& lo, float& hi) {
    asm("mov.b64 {%0, %1}, %2;" : "=f"(lo), "=f"(hi) : "l"(v));
}
__device__ __forceinline__ ull add2(ull a, ull b) {
    ull r; asm("add.rn.f32x2 %0, %1, %2;" : "=l"(r) : "l"(a), "l"(b)); return r;
}
__device__ __forceinline__ ull mul2(ull a, ull b) {
    ull r; asm("mul.rn.f32x2 %0, %1, %2;" : "=l"(r) : "l"(a), "l"(b)); return r;
}
__device__ __forceinline__ ull fma2(ull a, ull b, ull c) {
    ull r; asm("fma.rn.f32x2 %0, %1, %2, %3;" : "=l"(r) : "l"(a), "l"(b), "l"(c)); return r;
}
// keep `a` on tie (earlier kernel has priority) -> FSETP(|.|)+FSEL, 2 ops
__device__ __forceinline__ float selmin(float a, float b) {
    return (fabsf(b) < fabsf(a)) ? b : a;
}
// fire-and-forget 8-byte global->shared copy (LDGSTS)
__device__ __forceinline__ void cpa8(u32 smem_dst, const float* gsrc) {
    asm volatile("cp.async.ca.shared.global [%0], [%1], 8;\n"
                 :: "r"(smem_dst), "l"(gsrc) : "memory");
}

// ---------------------------------------------------------------------------
// HWC -> CHW planar (float4-vectorized, 4 pixels/thread)
// ---------------------------------------------------------------------------
__global__ void hwc2chw_kernel(const float* __restrict__ img) {
    int p = blockIdx.x * blockDim.x + threadIdx.x;
    if (p >= HW / 4) return;
    const float4* in = (const float4*)img + 3 * p;
    float4 a = in[0], b = in[1], c = in[2];
    ((float4*)(g_bufA + 0 * HW))[p] = make_float4(a.x, a.w, b.z, c.y);
    ((float4*)(g_bufA + 1 * HW))[p] = make_float4(a.y, b.x, b.w, c.z);
    ((float4*)(g_bufA + 2 * HW))[p] = make_float4(a.z, b.y, c.x, c.w);
}

// ---------------------------------------------------------------------------
// One SWF iteration. Tile: 128 wide x 32 high per block (32,4)=128 threads.
// Each WARP owns an 8-row output strip and a PRIVATE smem buffer of its 12
// input rows (8 + 4 halo). No __syncthreads().
// LDGSTS split into two commit groups (rows 0-7, rows 8-11); compute on
// iters 0-3 overlaps the in-flight group B, wait_group 0 before iter 4.
// Each thread: 4 adjacent columns (two packed f32x2 streams) x 8 rows.
// Channels per row: H0=(h0,h1) H1=(h2,h3) H2=(h4,h5) (h_i = v_i+v_{i+1}+v_{i+2})
//                   C0=(v2,v3) C1=(v4,v5)
// Vertical: B(p)=H(p+2)+H(p+3)+H(p+4) fresh, A(p)=B(p-2) from a 2-slot pipe.
// ---------------------------------------------------------------------------
#define TX 128
#define TY 32
#define PY 8
#define WROWS 12
#define STRIDE 136

__global__ __launch_bounds__(128, 7) void swf_step_kernel(int srcIsA) {
    const float* __restrict__ src = (srcIsA ? g_bufA : g_bufB) + blockIdx.z * HW;
    float* __restrict__ dst       = (srcIsA ? g_bufB : g_bufA) + blockIdx.z * HW;

    __shared__ float tile[4 * WROWS * STRIDE];

    const int tx = threadIdx.x, ty = threadIdx.y;
    const int bx = blockIdx.x * TX, by = blockIdx.y * TY;
    float* wtile = tile + ty * (WROWS * STRIDE);   // this warp's private buffer
    const int wrow0 = by + ty * PY - 2;            // global row of wtile row 0

    const bool interior = (blockIdx.x > 0) && (blockIdx.x < gridDim.x - 1) &&
                          (blockIdx.y > 0) && (blockIdx.y < gridDim.y - 1);

    if (interior) {
        const float* g = src + wrow0 * IMG_W + (bx - 2) + 2 * tx;
        u32 td = (u32)__cvta_generic_to_shared(wtile) + (4 + 2 * tx) * 4;
        // group A: rows 0..7 (prologue + iters 0-3)
        #pragma unroll
        for (int r = 0; r < 8; r++) {
            cpa8(td + r * (STRIDE * 4),       g + r * IMG_W);
            cpa8(td + r * (STRIDE * 4) + 256, g + r * IMG_W + 64);
            if (tx < 2)
                cpa8(td + r * (STRIDE * 4) + 512, g + r * IMG_W + 128);
        }
        asm volatile("cp.async.commit_group;\n" ::: "memory");
        // group B: rows 8..11 (iters 4-7)
        #pragma unroll
        for (int r = 8; r < WROWS; r++) {
            cpa8(td + r * (STRIDE * 4),       g + r * IMG_W);
            cpa8(td + r * (STRIDE * 4) + 256, g + r * IMG_W + 64);
            if (tx < 2)
                cpa8(td + r * (STRIDE * 4) + 512, g + r * IMG_W + 128);
        }
        asm volatile("cp.async.commit_group;\n" ::: "memory");
    } else {
        #pragma unroll
        for (int r = 0; r < WROWS; r++) {
            int gy = min(max(wrow0 + r, 0), IMG_H - 1);
            const float* grow = src + gy * IMG_W;
            #pragma unroll
            for (int k = 0; k < 2; k++) {
                int idx = tx + 32 * k;
                int c0 = min(max(bx - 2 + 2 * idx, 0), IMG_W - 1);
                int c1 = min(max(bx - 1 + 2 * idx, 0), IMG_W - 1);
                *(float2*)&wtile[r * STRIDE + 4 + 2 * idx] = make_float2(grow[c0], grow[c1]);
            }
            if (tx < 2) {
                int idx = tx + 64;
                int c0 = min(max(bx - 2 + 2 * idx, 0), IMG_W - 1);
                int c1 = min(max(bx - 1 + 2 * idx, 0), IMG_W - 1);
                *(float2*)&wtile[r * STRIDE + 4 + 2 * idx] = make_float2(grow[c0], grow[c1]);
            }
        }
    }
    // wait for group A only (boundary path: no groups pending -> no-op)
    asm volatile("cp.async.wait_group 1;\n" ::: "memory");
    __syncwarp();

    auto loadrow = [&](int r, ull* o) {
        const float* base = &wtile[r * STRIDE + 4 * tx + 4];
        float4 q0 = *(const float4*)(base);      // v0 v1 v2 v3
        float4 q1 = *(const float4*)(base + 4);  // v4 v5 v6 v7
        float s0 = q0.x + q0.y, s1 = q0.y + q0.z, s2 = q0.z + q0.w;
        float s3 = q0.w + q1.x, s4 = q1.x + q1.y, s5 = q1.y + q1.z;
        o[0] = pk(s0 + q0.z, s1 + q0.w);   // H0
        o[1] = pk(s2 + q1.x, s3 + q1.y);   // H1
        o[2] = pk(s4 + q1.z, s5 + q1.w);   // H2
        o[3] = pk(q0.z, q0.w);             // C0
        o[4] = pk(q1.x, q1.y);             // C1
    };

    const ull K9    = 0x4110000041100000ULL;  // ( 9, 9)
    const ull Km9   = 0xC1100000C1100000ULL;  // (-9,-9)
    const ull K15   = 0x4170000041700000ULL;  // (15,15)
    const ull Km135 = 0xC3070000C3070000ULL;  // (-135,-135)
    const float INV135 = 1.0f / 135.0f;

    // ---- prologue: strip rows 0..3 (wtile-local). Ring slot = row % 3. ----
    ull R[3][5], Ap[2][5];
    {
        ull t0[5], t1[5];
        loadrow(0, t0);
        loadrow(1, t1);
        loadrow(2, R[2]);   // row 2 -> slot 2
        loadrow(3, R[0]);   // row 3 -> slot 0
        #pragma unroll
        for (int ch = 0; ch < 5; ch++) {
            ull s = add2(t1[ch], R[2][ch]);
            Ap[0][ch] = add2(t0[ch], s);        // V(0..2) = A(0)
            Ap[1][ch] = add2(s, R[0][ch]);      // V(1..3) = A(1)
        }
    }

    float* drow = dst + (by + ty * PY) * IMG_W + bx + 4 * tx;

    #pragma unroll
    for (int p = 0; p < PY; p++) {
        if (p == 4) {  // rows 8..11 (group B) first needed here
            asm volatile("cp.async.wait_group 0;\n" ::: "memory");
            __syncwarp();
        }

        const int snew = (p + 4) % 3;   // incoming row p+4
        const int smid = (p + 2) % 3;   // middle row p+2
        const int s3   = (p + 3) % 3;   // row p+3

        loadrow(p + 4, R[snew]);

        ull B[5];
        #pragma unroll
        for (int ch = 0; ch < 5; ch++)
            B[ch] = add2(add2(R[smid][ch], R[s3][ch]), R[snew][ch]);  // V(p+2..p+4)

        const ull* A = Ap[p & 1];
        const ull* M = R[smid];

        // shared window sums across both streams
        ull AB0 = add2(A[0], B[0]);
        ull AB1 = add2(A[1], B[1]);
        ull AB2 = add2(A[2], B[2]);
        ull A01 = add2(A[0], A[1]);
        ull A12 = add2(A[1], A[2]);
        ull B01 = add2(B[0], B[1]);
        ull B12 = add2(B[1], B[2]);

        float4 outv;

        {   // stream 0: cols c0,c1  (Hl=H0, Hr=H1, cc=C0)
            ull negC = mul2(M[3], Km135);
            ull eL  = fma2(M[0], Km9, fma2(AB0, K9, negC));
            ull eR  = fma2(M[1], Km9, fma2(AB1, K9, negC));
            ull eU  = fma2(A[3], Km9, fma2(A01, K9, negC));
            ull eD  = fma2(B[3], Km9, fma2(B01, K9, negC));
            ull eNW = fma2(A[0], K15, negC);
            ull eNE = fma2(A[1], K15, negC);
            ull eSW = fma2(B[0], K15, negC);
            ull eSE = fma2(B[1], K15, negC);

            float c0, c1;   upk(M[3], c0, c1);
            float l0, l1;   upk(eL,  l0, l1);
            float r0, r1;   upk(eR,  r0, r1);
            float u0, u1;   upk(eU,  u0, u1);
            float d0, d1;   upk(eD,  d0, d1);
            float nw0, nw1; upk(eNW, nw0, nw1);
            float ne0, ne1; upk(eNE, ne0, ne1);
            float sw0, sw1; upk(eSW, sw0, sw1);
            float se0, se1; upk(eSE, se0, se1);

            float m0 = selmin(selmin(selmin(l0, r0), selmin(u0, d0)),
                              selmin(selmin(nw0, ne0), selmin(sw0, se0)));
            float m1 = selmin(selmin(selmin(l1, r1), selmin(u1, d1)),
                              selmin(selmin(nw1, ne1), selmin(sw1, se1)));
            outv.x = fmaf(m0, INV135, c0);
            outv.y = fmaf(m1, INV135, c1);
        }
        {   // stream 1: cols c2,c3  (Hl=H1, Hr=H2, cc=C1)
            ull negC = mul2(M[4], Km135);
            ull eL  = fma2(M[1], Km9, fma2(AB1, K9, negC));
            ull eR  = fma2(M[2], Km9, fma2(AB2, K9, negC));
            ull eU  = fma2(A[4], Km9, fma2(A12, K9, negC));
            ull eD  = fma2(B[4], Km9, fma2(B12, K9, negC));
            ull eNW = fma2(A[1], K15, negC);
            ull eNE = fma2(A[2], K15, negC);
            ull eSW = fma2(B[1], K15, negC);
            ull eSE = fma2(B[2], K15, negC);

            float c0, c1;   upk(M[4], c0, c1);
            float l0, l1;   upk(eL,  l0, l1);
            float r0, r1;   upk(eR,  r0, r1);
            float u0, u1;   upk(eU,  u0, u1);
            float d0, d1;   upk(eD,  d0, d1);
            float nw0, nw1; upk(eNW, nw0, nw1);
            float ne0, ne1; upk(eNE, ne0, ne1);
            float sw0, sw1; upk(eSW, sw0, sw1);
            float se0, se1; upk(eSE, se0, se1);

            float m0 = selmin(selmin(selmin(l0, r0), selmin(u0, d0)),
                              selmin(selmin(nw0, ne0), selmin(sw0, se0)));
            float m1 = selmin(selmin(selmin(l1, r1), selmin(u1, d1)),
                              selmin(selmin(nw1, ne1), selmin(sw1, se1)));
            outv.z = fmaf(m0, INV135, c0);
            outv.w = fmaf(m1, INV135, c1);
        }

        *(float4*)drow = outv;
        drow += IMG_W;

        #pragma unroll
        for (int ch = 0; ch < 5; ch++) Ap[p & 1][ch] = B[ch];  // A(p+2) = B(p)
    }
}

// ---------------------------------------------------------------------------
// |x0 - res| clipped, CHW -> HWC (float4-vectorized, 4 pixels/thread)
// ---------------------------------------------------------------------------
__global__ void finalize_kernel(const float* __restrict__ img, float* __restrict__ out) {
    int p = blockIdx.x * blockDim.x + threadIdx.x;
    if (p >= HW / 4) return;
    const float4* in = (const float4*)img + 3 * p;
    float4 a = in[0], b = in[1], c = in[2];
    float4 r0 = ((const float4*)(g_bufA + 0 * HW))[p];
    float4 r1 = ((const float4*)(g_bufA + 1 * HW))[p];
    float4 r2 = ((const float4*)(g_bufA + 2 * HW))[p];
    float4 o0 = make_float4(fminf(fabsf(a.x - r0.x), 255.f), fminf(fabsf(a.y - r1.x), 255.f),
                            fminf(fabsf(a.z - r2.x), 255.f), fminf(fabsf(a.w - r0.y), 255.f));
    float4 o1 = make_float4(fminf(fabsf(b.x - r1.y), 255.f), fminf(fabsf(b.y - r2.y), 255.f),
                            fminf(fabsf(b.z - r0.z), 255.f), fminf(fabsf(b.w - r1.z), 255.f));
    float4 o2 = make_float4(fminf(fabsf(c.x - r2.z), 255.f), fminf(fabsf(c.y - r0.w), 255.f),
                            fminf(fabsf(c.z - r1.w), 255.f), fminf(fabsf(c.w - r2.w), 255.f));
    float4* op = (float4*)out + 3 * p;
    op[0] = o0; op[1] = o1; op[2] = o2;
}

// ---------------------------------------------------------------------------
extern "C" void kernel_launch(void* const* d_in, const int* in_sizes, int n_in,
                              void* d_out, int out_size) {
    const float* img = (const float*)d_in[0];
    float* out = (float*)d_out;

    hwc2chw_kernel<<<HW / 4 / 256, 256>>>(img);

    dim3 grid(IMG_W / TX, IMG_H / TY, NCH);
    dim3 block(32, 4);
    for (int it = 0; it < ITER; it++) {
        swf_step_kernel<<<grid, block>>>((it & 1) == 0 ? 1 : 0);
    }
    // After 8 iterations (even), result is back in g_bufA.
    finalize_kernel<<<HW / 4 / 256, 256>>>(img, out);
}

// round 15
// speedup vs baseline: 1.7154x; 1.0113x over previous
#include <cuda_runtime.h>
#include <cstdint>

#define IMG_H 2048
#define IMG_W 2048
#define HW (IMG_H * IMG_W)
#define NCH 3
#define ITER 8

// Ping-pong scratch planes (CHW, planar). Device globals: allowed scratch.
__device__ float g_bufA[NCH * HW];
__device__ float g_bufB[NCH * HW];

typedef unsigned long long ull;
typedef unsigned int u32;

// ---------------- packed f32x2 helpers (Blackwell dual-FP32) ----------------
__device__ __forceinline__ ull pk(float lo, float hi) {
    ull r; asm("mov.b64 %0, {%1, %2};" : "=l"(r) : "f"(lo), "f"(hi)); return r;
}
__device__ __forceinline__ void upk(ull v, float& lo, float& hi) {
    asm("mov.b64 {%0, %1}, %2;" : "=f"(lo), "=f"(hi) : "l"(v));
}
__device__ __forceinline__ ull add2(ull a, ull b) {
    ull r; asm("add.rn.f32x2 %0, %1, %2;" : "=l"(r) : "l"(a), "l"(b)); return r;
}
__device__ __forceinline__ ull mul2(ull a, ull b) {
    ull r; asm("mul.rn.f32x2 %0, %1, %2;" : "=l"(r) : "l"(a), "l"(b)); return r;
}
__device__ __forceinline__ ull fma2(ull a, ull b, ull c) {
    ull r; asm("fma.rn.f32x2 %0, %1, %2, %3;" : "=l"(r) : "l"(a), "l"(b), "l"(c)); return r;
}
// keep `a` on tie (earlier kernel has priority) -> FSETP(|.|)+FSEL, 2 ops
__device__ __forceinline__ float selmin(float a, float b) {
    return (fabsf(b) < fabsf(a)) ? b : a;
}
// fire-and-forget 8-byte global->shared copy (LDGSTS)
__device__ __forceinline__ void cpa8(u32 smem_dst, const float* gsrc) {
    asm volatile("cp.async.ca.shared.global [%0], [%1], 8;\n"
                 :: "r"(smem_dst), "l"(gsrc) : "memory");
}

// ---------------------------------------------------------------------------
// HWC -> CHW planar (float4-vectorized, 4 pixels/thread)
// ---------------------------------------------------------------------------
__global__ void hwc2chw_kernel(const float* __restrict__ img) {
    int p = blockIdx.x * blockDim.x + threadIdx.x;
    if (p >= HW / 4) return;
    const float4* in = (const float4*)img + 3 * p;
    float4 a = in[0], b = in[1], c = in[2];
    ((float4*)(g_bufA + 0 * HW))[p] = make_float4(a.x, a.w, b.z, c.y);
    ((float4*)(g_bufA + 1 * HW))[p] = make_float4(a.y, b.x, b.w, c.z);
    ((float4*)(g_bufA + 2 * HW))[p] = make_float4(a.z, b.y, c.x, c.w);
}

// ---------------------------------------------------------------------------
// One SWF iteration. Tile: 128 wide x 32 high per block (32,4)=128 threads.
// Each WARP owns an 8-row output strip and a PRIVATE smem buffer of its 12
// input rows (8 + 4 halo). No __syncthreads().
// LDGSTS in THREE commit groups (rows 0-5 / 6-9 / 10-11); waits:
//   wait_group 2 before prologue (rows 0-3 + iters 0-1 need rows <=5)
//   wait_group 1 at p=2 (first use of row 6)
//   wait_group 0 at p=6 (first use of row 10)
// Each thread: 4 adjacent columns (two packed f32x2 streams) x 8 rows.
// Channels per row: H0=(h0,h1) H1=(h2,h3) H2=(h4,h5) (h_i = v_i+v_{i+1}+v_{i+2})
//                   C0=(v2,v3) C1=(v4,v5)
// Vertical: B(p)=H(p+2)+H(p+3)+H(p+4) fresh, A(p)=B(p-2) from a 2-slot pipe.
// ---------------------------------------------------------------------------
#define TX 128
#define TY 32
#define PY 8
#define WROWS 12
#define STRIDE 136

__global__ __launch_bounds__(128, 7) void swf_step_kernel(int srcIsA) {
    const float* __restrict__ src = (srcIsA ? g_bufA : g_bufB) + blockIdx.z * HW;
    float* __restrict__ dst       = (srcIsA ? g_bufB : g_bufA) + blockIdx.z * HW;

    __shared__ float tile[4 * WROWS * STRIDE];

    const int tx = threadIdx.x, ty = threadIdx.y;
    const int bx = blockIdx.x * TX, by = blockIdx.y * TY;
    float* wtile = tile + ty * (WROWS * STRIDE);   // this warp's private buffer
    const int wrow0 = by + ty * PY - 2;            // global row of wtile row 0

    const bool interior = (blockIdx.x > 0) && (blockIdx.x < gridDim.x - 1) &&
                          (blockIdx.y > 0) && (blockIdx.y < gridDim.y - 1);

    if (interior) {
        const float* g = src + wrow0 * IMG_W + (bx - 2) + 2 * tx;
        u32 td = (u32)__cvta_generic_to_shared(wtile) + (4 + 2 * tx) * 4;
        // group A: rows 0..5 (prologue + iters 0-1)
        #pragma unroll
        for (int r = 0; r < 6; r++) {
            cpa8(td + r * (STRIDE * 4),       g + r * IMG_W);
            cpa8(td + r * (STRIDE * 4) + 256, g + r * IMG_W + 64);
            if (tx < 2)
                cpa8(td + r * (STRIDE * 4) + 512, g + r * IMG_W + 128);
        }
        asm volatile("cp.async.commit_group;\n" ::: "memory");
        // group B: rows 6..9 (iters 2-5)
        #pragma unroll
        for (int r = 6; r < 10; r++) {
            cpa8(td + r * (STRIDE * 4),       g + r * IMG_W);
            cpa8(td + r * (STRIDE * 4) + 256, g + r * IMG_W + 64);
            if (tx < 2)
                cpa8(td + r * (STRIDE * 4) + 512, g + r * IMG_W + 128);
        }
        asm volatile("cp.async.commit_group;\n" ::: "memory");
        // group C: rows 10..11 (iters 6-7)
        #pragma unroll
        for (int r = 10; r < WROWS; r++) {
            cpa8(td + r * (STRIDE * 4),       g + r * IMG_W);
            cpa8(td + r * (STRIDE * 4) + 256, g + r * IMG_W + 64);
            if (tx < 2)
                cpa8(td + r * (STRIDE * 4) + 512, g + r * IMG_W + 128);
        }
        asm volatile("cp.async.commit_group;\n" ::: "memory");
    } else {
        #pragma unroll
        for (int r = 0; r < WROWS; r++) {
            int gy = min(max(wrow0 + r, 0), IMG_H - 1);
            const float* grow = src + gy * IMG_W;
            #pragma unroll
            for (int k = 0; k < 2; k++) {
                int idx = tx + 32 * k;
                int c0 = min(max(bx - 2 + 2 * idx, 0), IMG_W - 1);
                int c1 = min(max(bx - 1 + 2 * idx, 0), IMG_W - 1);
                *(float2*)&wtile[r * STRIDE + 4 + 2 * idx] = make_float2(grow[c0], grow[c1]);
            }
            if (tx < 2) {
                int idx = tx + 64;
                int c0 = min(max(bx - 2 + 2 * idx, 0), IMG_W - 1);
                int c1 = min(max(bx - 1 + 2 * idx, 0), IMG_W - 1);
                *(float2*)&wtile[r * STRIDE + 4 + 2 * idx] = make_float2(grow[c0], grow[c1]);
            }
        }
    }
    // wait for group A only (boundary path: no groups pending -> no-op)
    asm volatile("cp.async.wait_group 2;\n" ::: "memory");
    __syncwarp();

    auto loadrow = [&](int r, ull* o) {
        const float* base = &wtile[r * STRIDE + 4 * tx + 4];
        float4 q0 = *(const float4*)(base);      // v0 v1 v2 v3
        float4 q1 = *(const float4*)(base + 4);  // v4 v5 v6 v7
        float s0 = q0.x + q0.y, s1 = q0.y + q0.z, s2 = q0.z + q0.w;
        float s3 = q0.w + q1.x, s4 = q1.x + q1.y, s5 = q1.y + q1.z;
        o[0] = pk(s0 + q0.z, s1 + q0.w);   // H0
        o[1] = pk(s2 + q1.x, s3 + q1.y);   // H1
        o[2] = pk(s4 + q1.z, s5 + q1.w);   // H2
        o[3] = pk(q0.z, q0.w);             // C0
        o[4] = pk(q1.x, q1.y);             // C1
    };

    const ull K9    = 0x4110000041100000ULL;  // ( 9, 9)
    const ull Km9   = 0xC1100000C1100000ULL;  // (-9,-9)
    const ull K15   = 0x4170000041700000ULL;  // (15,15)
    const ull Km135 = 0xC3070000C3070000ULL;  // (-135,-135)
    const float INV135 = 1.0f / 135.0f;

    // ---- prologue: strip rows 0..3 (wtile-local). Ring slot = row % 3. ----
    ull R[3][5], Ap[2][5];
    {
        ull t0[5], t1[5];
        loadrow(0, t0);
        loadrow(1, t1);
        loadrow(2, R[2]);   // row 2 -> slot 2
        loadrow(3, R[0]);   // row 3 -> slot 0
        #pragma unroll
        for (int ch = 0; ch < 5; ch++) {
            ull s = add2(t1[ch], R[2][ch]);
            Ap[0][ch] = add2(t0[ch], s);        // V(0..2) = A(0)
            Ap[1][ch] = add2(s, R[0][ch]);      // V(1..3) = A(1)
        }
    }

    float* drow = dst + (by + ty * PY) * IMG_W + bx + 4 * tx;

    #pragma unroll
    for (int p = 0; p < PY; p++) {
        if (p == 2) {  // row 6 (group B) first needed here
            asm volatile("cp.async.wait_group 1;\n" ::: "memory");
            __syncwarp();
        }
        if (p == 6) {  // row 10 (group C) first needed here
            asm volatile("cp.async.wait_group 0;\n" ::: "memory");
            __syncwarp();
        }

        const int snew = (p + 4) % 3;   // incoming row p+4
        const int smid = (p + 2) % 3;   // middle row p+2
        const int s3   = (p + 3) % 3;   // row p+3

        loadrow(p + 4, R[snew]);

        ull B[5];
        #pragma unroll
        for (int ch = 0; ch < 5; ch++)
            B[ch] = add2(add2(R[smid][ch], R[s3][ch]), R[snew][ch]);  // V(p+2..p+4)

        const ull* A = Ap[p & 1];
        const ull* M = R[smid];

        // shared window sums across both streams
        ull AB0 = add2(A[0], B[0]);
        ull AB1 = add2(A[1], B[1]);
        ull AB2 = add2(A[2], B[2]);
        ull A01 = add2(A[0], A[1]);
        ull A12 = add2(A[1], A[2]);
        ull B01 = add2(B[0], B[1]);
        ull B12 = add2(B[1], B[2]);

        float4 outv;

        {   // stream 0: cols c0,c1  (Hl=H0, Hr=H1, cc=C0)
            ull negC = mul2(M[3], Km135);
            ull eL  = fma2(M[0], Km9, fma2(AB0, K9, negC));
            ull eR  = fma2(M[1], Km9, fma2(AB1, K9, negC));
            ull eU  = fma2(A[3], Km9, fma2(A01, K9, negC));
            ull eD  = fma2(B[3], Km9, fma2(B01, K9, negC));
            ull eNW = fma2(A[0], K15, negC);
            ull eNE = fma2(A[1], K15, negC);
            ull eSW = fma2(B[0], K15, negC);
            ull eSE = fma2(B[1], K15, negC);

            float c0, c1;   upk(M[3], c0, c1);
            float l0, l1;   upk(eL,  l0, l1);
            float r0, r1;   upk(eR,  r0, r1);
            float u0, u1;   upk(eU,  u0, u1);
            float d0, d1;   upk(eD,  d0, d1);
            float nw0, nw1; upk(eNW, nw0, nw1);
            float ne0, ne1; upk(eNE, ne0, ne1);
            float sw0, sw1; upk(eSW, sw0, sw1);
            float se0, se1; upk(eSE, se0, se1);

            float m0 = selmin(selmin(selmin(l0, r0), selmin(u0, d0)),
                              selmin(selmin(nw0, ne0), selmin(sw0, se0)));
            float m1 = selmin(selmin(selmin(l1, r1), selmin(u1, d1)),
                              selmin(selmin(nw1, ne1), selmin(sw1, se1)));
            outv.x = fmaf(m0, INV135, c0);
            outv.y = fmaf(m1, INV135, c1);
        }
        {   // stream 1: cols c2,c3  (Hl=H1, Hr=H2, cc=C1)
            ull negC = mul2(M[4], Km135);
            ull eL  = fma2(M[1], Km9, fma2(AB1, K9, negC));
            ull eR  = fma2(M[2], Km9, fma2(AB2, K9, negC));
            ull eU  = fma2(A[4], Km9, fma2(A12, K9, negC));
            ull eD  = fma2(B[4], Km9, fma2(B12, K9, negC));
            ull eNW = fma2(A[1], K15, negC);
            ull eNE = fma2(A[2], K15, negC);
            ull eSW = fma2(B[1], K15, negC);
            ull eSE = fma2(B[2], K15, negC);

            float c0, c1;   upk(M[4], c0, c1);
            float l0, l1;   upk(eL,  l0, l1);
            float r0, r1;   upk(eR,  r0, r1);
            float u0, u1;   upk(eU,  u0, u1);
            float d0, d1;   upk(eD,  d0, d1);
            float nw0, nw1; upk(eNW, nw0, nw1);
            float ne0, ne1; upk(eNE, ne0, ne1);
            float sw0, sw1; upk(eSW, sw0, sw1);
            float se0, se1; upk(eSE, se0, se1);

            float m0 = selmin(selmin(selmin(l0, r0), selmin(u0, d0)),
                              selmin(selmin(nw0, ne0), selmin(sw0, se0)));
            float m1 = selmin(selmin(selmin(l1, r1), selmin(u1, d1)),
                              selmin(selmin(nw1, ne1), selmin(sw1, se1)));
            outv.z = fmaf(m0, INV135, c0);
            outv.w = fmaf(m1, INV135, c1);
        }

        *(float4*)drow = outv;
        drow += IMG_W;

        #pragma unroll
        for (int ch = 0; ch < 5; ch++) Ap[p & 1][ch] = B[ch];  // A(p+2) = B(p)
    }
}

// ---------------------------------------------------------------------------
// |x0 - res| clipped, CHW -> HWC (float4-vectorized, 4 pixels/thread)
// ---------------------------------------------------------------------------
__global__ void finalize_kernel(const float* __restrict__ img, float* __restrict__ out) {
    int p = blockIdx.x * blockDim.x + threadIdx.x;
    if (p >= HW / 4) return;
    const float4* in = (const float4*)img + 3 * p;
    float4 a = in[0], b = in[1], c = in[2];
    float4 r0 = ((const float4*)(g_bufA + 0 * HW))[p];
    float4 r1 = ((const float4*)(g_bufA + 1 * HW))[p];
    float4 r2 = ((const float4*)(g_bufA + 2 * HW))[p];
    float4 o0 = make_float4(fminf(fabsf(a.x - r0.x), 255.f), fminf(fabsf(a.y - r1.x), 255.f),
                            fminf(fabsf(a.z - r2.x), 255.f), fminf(fabsf(a.w - r0.y), 255.f));
    float4 o1 = make_float4(fminf(fabsf(b.x - r1.y), 255.f), fminf(fabsf(b.y - r2.y), 255.f),
                            fminf(fabsf(b.z - r0.z), 255.f), fminf(fabsf(b.w - r1.z), 255.f));
    float4 o2 = make_float4(fminf(fabsf(c.x - r2.z), 255.f), fminf(fabsf(c.y - r0.w), 255.f),
                            fminf(fabsf(c.z - r1.w), 255.f), fminf(fabsf(c.w - r2.w), 255.f));
    float4* op = (float4*)out + 3 * p;
    op[0] = o0; op[1] = o1; op[2] = o2;
}

// ---------------------------------------------------------------------------
extern "C" void kernel_launch(void* const* d_in, const int* in_sizes, int n_in,
                              void* d_out, int out_size) {
    const float* img = (const float*)d_in[0];
    float* out = (float*)d_out;

    hwc2chw_kernel<<<HW / 4 / 256, 256>>>(img);

    dim3 grid(IMG_W / TX, IMG_H / TY, NCH);
    dim3 block(32, 4);
    for (int it = 0; it < ITER; it++) {
        swf_step_kernel<<<grid, block>>>((it & 1) == 0 ? 1 : 0);
    }
    // After 8 iterations (even), result is back in g_bufA.
    finalize_kernel<<<HW / 4 / 256, 256>>>(img, out);
}